// round 8
// baseline (speedup 1.0000x reference)
#include <cuda_runtime.h>

// Problem constants (fixed shapes from reference setup_inputs)
#define T_STEPS 15
#define CIN     64
#define COUT    128
#define H_IN    256
#define W_IN    256
#define HO      252
#define WO      252
#define KH_     5
#define KW_     5
#define KWIN    16
#define PER_CO  (CIN * KH_ * KW_)          // 1600
#define TOTAL   (COUT * PER_CO)            // 204800
#define HEAVY_ELEMS (KWIN * PER_CO)        // 25600
#define HEAVY_ACTIVE 200                   // active heavy threads per block
#define HEAVY_BLOCKS (HEAVY_ELEMS / HEAVY_ACTIVE)   // 128 blocks -> 128 SMs busy
#define COPY_VEC (TOTAL / 4)               // 51200 float4 threads
#define COPY_BLOCKS (COPY_VEC / 256)       // 200

__global__ __launch_bounds__(256)
void stdp_split5_kernel(const float* __restrict__ in_spk,      // [T, CIN, H, W]
                        const float* __restrict__ out_spk,     // [T, COUT, HO, WO]
                        const long long* __restrict__ winners, // [K, 3] int64
                        const float* __restrict__ weight,      // [COUT, CIN, KH, KW]
                        const float* __restrict__ ltp,         // [COUT]
                        const float* __restrict__ ltd,         // [COUT]
                        float* __restrict__ out)               // [COUT, CIN, KH, KW]
{
    int bid = blockIdx.x;

    if (bid < HEAVY_BLOCKS) {
        // ---- Winner region: one thread per (winner, ci, kh, kw);
        //      30 independent loads -> MLP=30. 200 active threads/block,
        //      128 blocks so 128 SMs carry the gather tail. ----
        if (threadIdx.x >= HEAVY_ACTIVE) return;
        int gpos = bid * HEAVY_ACTIVE + threadIdx.x; // 0 .. 25599
        int k    = gpos / PER_CO;                    // winner index 0..15
        int rem  = gpos - k * PER_CO;                // 0..1599
        int ci   = rem / (KH_ * KW_);
        int kk   = rem - ci * (KH_ * KW_);
        int kh   = kk / KW_;
        int kw   = kk - kh * KW_;

        int f = (int)__ldg(&winners[3 * k + 0]);     // winner channel (unique: permutation)
        int r = (int)__ldg(&winners[3 * k + 1]);
        int c = (int)__ldg(&winners[3 * k + 2]);

        int widx = f * PER_CO + rem;
        float w = __ldg(&weight[widx]);

        // r,c in [0,252): r+kh <= 255, c+kw <= 255 — always in bounds.
        // All offsets fit in int32 (max ~122M elements).
        const int in_stride_t  = CIN  * H_IN * W_IN;   // 4,194,304
        const int out_stride_t = COUT * HO   * WO;     // 8,128,512
        int in_off  = ci * (H_IN * W_IN) + (r + kh) * W_IN + (c + kw);
        int out_off = f * (HO * WO) + r * WO + c;

        float psum = 0.0f, osum = 0.0f;
        #pragma unroll
        for (int t = 0; t < T_STEPS; t++) {
            psum += __ldg(&in_spk [t * in_stride_t  + in_off ]);
            osum += __ldg(&out_spk[t * out_stride_t + out_off]);
        }
        float lr = (psum >= osum) ? __ldg(&ltp[f]) : __ldg(&ltd[f]);
        float nw = w + lr * (w * (1.0f - w));
        out[widx] = fminf(fmaxf(nw, 0.0f), 1.0f);
    } else {
        // ---- Copy region: float4 clip of non-winner rows; predicated store. ----
        int v   = (bid - HEAVY_BLOCKS) * 256 + threadIdx.x;   // 0 .. 51199
        int co  = (v * 4) / PER_CO;                           // float4 stays in one co row

        bool is_winner = false;
        #pragma unroll
        for (int k = 0; k < KWIN; k++) {
            if ((int)__ldg(&winners[3 * k]) == co) is_winner = true;
        }

        float4 w4 = __ldg(((const float4*)weight) + v);
        w4.x = fminf(fmaxf(w4.x, 0.0f), 1.0f);
        w4.y = fminf(fmaxf(w4.y, 0.0f), 1.0f);
        w4.z = fminf(fmaxf(w4.z, 0.0f), 1.0f);
        w4.w = fminf(fmaxf(w4.w, 0.0f), 1.0f);
        if (!is_winner) {
            ((float4*)out)[v] = w4;
        }
    }
}

extern "C" void kernel_launch(void* const* d_in, const int* in_sizes, int n_in,
                              void* d_out, int out_size)
{
    const float*     in_spk  = (const float*)d_in[0];
    const float*     out_spk = (const float*)d_in[1];
    const long long* winners = (const long long*)d_in[2];
    const float*     weight  = (const float*)d_in[3];
    const float*     ltp     = (const float*)d_in[4];
    const float*     ltd     = (const float*)d_in[5];
    float*           out     = (float*)d_out;

    stdp_split5_kernel<<<HEAVY_BLOCKS + COPY_BLOCKS, 256>>>(
        in_spk, out_spk, winners, weight, ltp, ltd, out);
}

// round 10
// speedup vs baseline: 1.0385x; 1.0385x over previous
#include <cuda_runtime.h>

// Problem constants (fixed shapes from reference setup_inputs)
#define T_STEPS 15
#define CIN     64
#define COUT    128
#define H_IN    256
#define W_IN    256
#define HO      252
#define WO      252
#define KH_     5
#define KW_     5
#define KWIN    16
#define PER_CO  (CIN * KH_ * KW_)          // 1600
#define TOTAL   (COUT * PER_CO)            // 204800
#define HEAVY_ELEMS (KWIN * PER_CO)        // 25600
#define HEAVY_BLOCKS (HEAVY_ELEMS / 256)   // 100
#define COPY_VEC (TOTAL / 4)               // 51200 float4 threads
#define COPY_BLOCKS (COPY_VEC / 256)       // 200

__global__ __launch_bounds__(256)
void stdp_split_kernel(const float* __restrict__ in_spk,      // [T, CIN, H, W]
                       const float* __restrict__ out_spk,     // [T, COUT, HO, WO]
                       const long long* __restrict__ winners, // [K, 3] int64
                       const float* __restrict__ weight,      // [COUT, CIN, KH, KW]
                       const float* __restrict__ ltp,         // [COUT]
                       const float* __restrict__ ltd,         // [COUT]
                       float* __restrict__ out)               // [COUT, CIN, KH, KW]
{
    int bid = blockIdx.x;

    if (bid < HEAVY_BLOCKS) {
        // ---- Winner region: one thread per (winner, ci, kh, kw); 30 fully
        //      independent loads -> MLP=30 per thread. Scheduled first so the
        //      gather latency overlaps the streaming copy. ----
        int gpos = bid * 256 + threadIdx.x;          // 0 .. 25599
        int k    = gpos / PER_CO;                    // winner index 0..15
        int rem  = gpos - k * PER_CO;                // 0..1599
        int ci   = rem / (KH_ * KW_);
        int kk   = rem - ci * (KH_ * KW_);
        int kh   = kk / KW_;
        int kw   = kk - kh * KW_;

        int f = (int)__ldg(&winners[3 * k + 0]);     // winner channel (unique: permutation)
        int r = (int)__ldg(&winners[3 * k + 1]);
        int c = (int)__ldg(&winners[3 * k + 2]);

        long widx = (long)f * PER_CO + rem;
        float w = __ldg(&weight[widx]);

        // r,c in [0,252): r+kh <= 255, c+kw <= 255 — always in bounds.
        const long in_stride_t  = (long)CIN  * H_IN * W_IN;   // 4,194,304
        const long out_stride_t = (long)COUT * HO   * WO;     // 8,128,512
        long in_off  = (long)ci * H_IN * W_IN + (long)(r + kh) * W_IN + (c + kw);
        long out_off = (long)f * HO * WO + (long)r * WO + c;

        float psum = 0.0f, osum = 0.0f;
        #pragma unroll
        for (int t = 0; t < T_STEPS; t++) {
            psum += __ldg(&in_spk [t * in_stride_t  + in_off ]);
            osum += __ldg(&out_spk[t * out_stride_t + out_off]);
        }
        float lr = (psum >= osum) ? __ldg(&ltp[f]) : __ldg(&ltd[f]);
        float nw = w + lr * (w * (1.0f - w));
        out[widx] = fminf(fmaxf(nw, 0.0f), 1.0f);
    } else {
        // ---- Copy region: float4 clip of non-winner rows ----
        int v   = (bid - HEAVY_BLOCKS) * 256 + threadIdx.x;   // 0 .. 51199
        int co  = (v * 4) / PER_CO;                            // float4 stays in one co row

        // Is co a winner channel? (heavy region writes those rows)
        bool is_winner = false;
        #pragma unroll
        for (int k = 0; k < KWIN; k++) {
            if ((int)__ldg(&winners[3 * k]) == co) is_winner = true;
        }
        if (is_winner) return;

        float4 w4 = __ldg(((const float4*)weight) + v);
        w4.x = fminf(fmaxf(w4.x, 0.0f), 1.0f);
        w4.y = fminf(fmaxf(w4.y, 0.0f), 1.0f);
        w4.z = fminf(fmaxf(w4.z, 0.0f), 1.0f);
        w4.w = fminf(fmaxf(w4.w, 0.0f), 1.0f);
        ((float4*)out)[v] = w4;
    }
}

extern "C" void kernel_launch(void* const* d_in, const int* in_sizes, int n_in,
                              void* d_out, int out_size)
{
    const float*     in_spk  = (const float*)d_in[0];
    const float*     out_spk = (const float*)d_in[1];
    const long long* winners = (const long long*)d_in[2];
    const float*     weight  = (const float*)d_in[3];
    const float*     ltp     = (const float*)d_in[4];
    const float*     ltd     = (const float*)d_in[5];
    float*           out     = (float*)d_out;

    stdp_split_kernel<<<HEAVY_BLOCKS + COPY_BLOCKS, 256>>>(
        in_spk, out_spk, winners, weight, ltp, ltd, out);
}